// round 10
// baseline (speedup 1.0000x reference)
#include <cuda_runtime.h>
#include <math.h>
#include <stdint.h>

#define NMAXN 10000
#define NT 10
#define TN 10
#define KNB 16
#define K1 17
#define MAXB 128
#define DD 128
#define FULL 0xffffffffu
#define NEG2 -1.0e9f
#define LK2C (-14.426950408889634f)   /* -(1/REG)*log2(e), REG=0.1 */
#define LQ2C (-3.3219280948873623f)   /* log2(1/10) */
#define C26  (LQ2C + 26.0f)

// ---------------- device scratch ----------------
__device__ int g_is64;
__device__ int g_cnt[NMAXN];
__device__ int g_bucket[NMAXN * MAXB];
__device__ int g_nbrs[NMAXN * KNB];
__device__ int g_cnt16[NMAXN];
__device__ unsigned g_c1[NMAXN * K1];
__device__ float g_M[(size_t)NMAXN * NT * K1 * TN];   // [pair][a][b], 68 MB

__device__ __forceinline__ float ex2f(float x) {
    float r; asm("ex2.approx.ftz.f32 %0, %1;" : "=f"(r) : "f"(x)); return r;
}
__device__ __forceinline__ float lg2f_(float x) {
    float r; asm("lg2.approx.ftz.f32 %0, %1;" : "=f"(r) : "f"(x)); return r;
}
__device__ __forceinline__ float rcpf_(float x) {
    float r; asm("rcp.approx.ftz.f32 %0, %1;" : "=f"(r) : "f"(x)); return r;
}
// warp max of f32 via order-preserving int mapping + integer redux
__device__ __forceinline__ float warpmaxf(float v) {
    unsigned b = __float_as_uint(v);
    unsigned key = ((int)b < 0) ? ~b : (b ^ 0x80000000u);
    unsigned r = __reduce_max_sync(FULL, key);
    unsigned rb = (r & 0x80000000u) ? (r ^ 0x80000000u) : ~r;
    return __uint_as_float(rb);
}

// ---------------- launch 1: zero counters + dtype sniff ----------------------
__global__ void k_init(const int* ei, int n) {
    int t = blockIdx.x * blockDim.x + threadIdx.x;
    if (t < n) g_cnt[t] = 0;
    if (t == 0) {
        int ok = 1;
        for (int j = 0; j < 50; j++) if (ei[2 * j + 1] != 0) ok = 0;
        g_is64 = ok;
    }
}

// ---------------- launch 2: bucket edges by src ------------------------------
__global__ void k_bucket(const int* ei, int e) {
    int t = blockIdx.x * blockDim.x + threadIdx.x;
    if (t >= e) return;
    int s = g_is64 ? ei[2 * t] : ei[t];
    int pos = atomicAdd(&g_cnt[s], 1);
    if (pos < MAXB) g_bucket[s * MAXB + pos] = t;
}

// ------ launch 3: per node keep dsts of the 16 smallest edge indices ---------
__global__ void k_select(const int* ei, int n, int e) {
    int i = blockIdx.x * blockDim.x + threadIdx.x;
    if (i >= n) return;
    int is64 = g_is64;
    int c = g_cnt[i]; if (c > MAXB) c = MAXB;
    int arr[MAXB];
    for (int j = 0; j < c; j++) arr[j] = g_bucket[i * MAXB + j];
    int k16 = c < KNB ? c : KNB;
    for (int k = 0; k < k16; k++) {
        int mp = k;
        for (int j = k + 1; j < c; j++) if (arr[j] < arr[mp]) mp = j;
        int t = arr[k]; arr[k] = arr[mp]; arr[mp] = t;
        int eidx = arr[k];
        int dst = is64 ? ei[2 * (e + eidx)] : ei[e + eidx];
        g_nbrs[i * KNB + k] = dst;
    }
    g_cnt16[i] = k16;
}

// ---------------- launch 4: warp per node, C1 adjacency bitmasks -------------
__global__ void __launch_bounds__(128) k_c1(int n) {
    int gw = (blockIdx.x * blockDim.x + threadIdx.x) >> 5;
    int lane = threadIdx.x & 31;
    if (gw >= n) return;
    int i = gw;
    int c16 = g_cnt16[i];
    int myid = -1;
    if (lane == 0) myid = i;
    else if (lane < K1 && (lane - 1) < c16) myid = g_nbrs[i * KNB + lane - 1];
    int cA = (myid >= 0) ? g_cnt16[myid] : 0;
    int nb[KNB];
#pragma unroll
    for (int j = 0; j < KNB; j++)
        nb[j] = (myid >= 0 && j < cA) ? g_nbrs[myid * KNB + j] : -2;
    unsigned msk = 0u;
#pragma unroll
    for (int b = 0; b < K1; b++) {
        int sb = __shfl_sync(FULL, myid, b);
        bool hit = false;
#pragma unroll
        for (int j = 0; j < KNB; j++) hit |= (nb[j] == sb);
        if (myid >= 0 && sb >= 0 && hit) msk |= (1u << b);
    }
    if (lane < K1) g_c1[i * K1 + lane] = msk;
}

// ---------------- launch 5: block per node, M[pair][a][b] --------------------
__global__ void __launch_bounds__(128) k_M(const float* __restrict__ x,
                                           const float* __restrict__ tf, int n) {
    __shared__ float xs[K1][DD];
    __shared__ float sxn[K1];
    __shared__ int sS[K1];
    int i = blockIdx.x, tid = threadIdx.x;
    int c16 = g_cnt16[i];
    if (tid < K1) {
        int v;
        if (tid == 0) v = i;
        else v = (tid - 1 < c16) ? g_nbrs[i * KNB + tid - 1] : -1;
        sS[tid] = v;
    }
    __syncthreads();
    for (int a = 0; a < K1; a++) {
        int sv = sS[a];
        xs[a][tid] = (sv >= 0) ? x[(size_t)sv * DD + tid] : 0.f;
    }
    __syncthreads();
    if (tid < K1) {
        float s = 0.f;
        for (int d = 0; d < DD; d++) { float v = xs[tid][d]; s = fmaf(v, v, s); }
        sxn[tid] = s;
    }
    __syncthreads();
    if (tid < NT * TN) {
        int tt = tid / TN, b = tid % TN;
        const float4* fr = reinterpret_cast<const float4*>(tf + ((size_t)tt * TN + b) * DD);
        float acc[K1];
        float fb = 0.f;
#pragma unroll
        for (int a = 0; a < K1; a++) acc[a] = 0.f;
        for (int c = 0; c < DD / 4; c++) {
            float4 f4 = __ldg(fr + c);
            fb = fmaf(f4.x, f4.x, fmaf(f4.y, f4.y, fmaf(f4.z, f4.z, fmaf(f4.w, f4.w, fb))));
#pragma unroll
            for (int a = 0; a < K1; a++) {
                float4 x4 = *reinterpret_cast<const float4*>(&xs[a][c * 4]);
                acc[a] = fmaf(x4.x, f4.x, fmaf(x4.y, f4.y, fmaf(x4.z, f4.z, fmaf(x4.w, f4.w, acc[a]))));
            }
        }
        float* Mo = g_M + ((size_t)i * NT + tt) * (K1 * TN) + b;
#pragma unroll
        for (int a = 0; a < K1; a++) Mo[a * TN] = sxn[a] + fb - 2.f * acc[a];
    }
}

// ---------------- launch 6: FGW, warp per (node, template) -------------------
__global__ void __launch_bounds__(128, 8) k_fgw(const float* __restrict__ C2g,
                                                float* __restrict__ out, int n) {
    __shared__ float sC2[NT][TN][TN];
    __shared__ float sc2r[NT][TN];
    __shared__ float sT[4][K1][TN];
    int tid = threadIdx.x;
    for (int idx = tid; idx < NT * TN * TN; idx += 128)
        (&sC2[0][0][0])[idx] = C2g[idx];
    __syncthreads();
    if (tid < NT * TN) {
        int tt = tid / TN, b = tid % TN;
        float s = 0.f;
        for (int c = 0; c < TN; c++) { float v = sC2[tt][b][c]; s = fmaf(v, v, s); }
        sc2r[tt][b] = s * (1.0f / TN);
    }
    __syncthreads();

    int w = tid >> 5, lane = tid & 31;
    long long pair = (long long)blockIdx.x * 4 + w;
    if (pair >= (long long)n * NT) return;
    int i = (int)(pair / NT), tt = (int)(pair % NT);

    int cnt1 = g_cnt16[i] + 1;
    bool vlane = lane < K1;
    bool vnode = lane < cnt1;
    float inv1 = 1.0f / (float)cnt1;
    unsigned m = vlane ? g_c1[i * K1 + lane] : 0u;
    const float* Mp = g_M + (size_t)pair * (K1 * TN) + lane * TN;   // L1-resident reloads
    float logp2 = vnode ? -log2f((float)cnt1) : NEG2;
    float CR = logp2 - LQ2C;
    float constC_a = (float)__popc(m) * inv1;

    float Trow[TN];
    float t0 = vnode ? (inv1 * (1.0f / TN)) : 0.f;
#pragma unroll
    for (int b = 0; b < TN; b++) Trow[b] = t0;
    if (vlane) {
#pragma unroll
        for (int b = 0; b < TN; b++) sT[w][lane][b] = Trow[b];
    }
    __syncwarp();

    for (int k = 0; k < 6; k++) {
        // tmp = C1 @ T (row a = my lane)
        float tmp[TN];
#pragma unroll
        for (int d = 0; d < TN; d++) tmp[d] = 0.f;
        for (int c = 0; c < K1; c++) {
            float wbit = (float)((m >> c) & 1u);
#pragma unroll
            for (int d = 0; d < TN; d++) tmp[d] = fmaf(wbit, sT[w][c][d], tmp[d]);
        }

        if (k == 5) {   // final distance
            float acc = 0.f;
            if (vlane) {
#pragma unroll
                for (int b = 0; b < TN; b++) {
                    float cr = 0.f;
#pragma unroll
                    for (int d = 0; d < TN; d++) cr = fmaf(tmp[d], sC2[tt][b][d], cr);
                    float tens = constC_a + sc2r[tt][b] - 2.f * cr;
                    acc += (0.5f * Mp[b] + 0.5f * tens) * Trow[b];
                }
            }
            for (int o = 16; o; o >>= 1) acc += __shfl_xor_sync(FULL, acc, o);
            if (lane == 0) out[pair] = acc;
            return;
        }

        // B = logK + f (f starts 0); pad lanes excluded via -1e30
        float B[TN], e[TN];
#pragma unroll
        for (int b = 0; b < TN; b++) {
            float cr = 0.f;
#pragma unroll
            for (int d = 0; d < TN; d++) cr = fmaf(tmp[d], sC2[tt][b][d], cr);
            float tens = constC_a + sc2r[tt][b] - 2.f * cr;
            B[b] = vlane ? (LK2C * (0.5f * Mp[b] + tens)) : -1e30f;
        }
        float f2 = 0.f;

        // ---- it0: full, max-based row step (rows unnormalized) ----
        {
            float g2[TN];
#pragma unroll
            for (int b = 0; b < TN; b++) {
                float v = B[b];
                float mbb = warpmaxf(v);
                float eb = ex2f(v - mbb + 26.f);          // max lane == 2^26 exact
                unsigned u = __float2uint_rn(eb);
                unsigned s = __reduce_add_sync(FULL, u);   // <= 17*2^26 < 2^32
                g2[b] = C26 - mbb - lg2f_((float)s);
            }
            float rm = -3.4e38f;
#pragma unroll
            for (int b = 0; b < TN; b++) { g2[b] += B[b]; rm = fmaxf(rm, g2[b]); }
            float S0 = 0.f;
#pragma unroll
            for (int b = 0; b < TN; b++) S0 += ex2f(g2[b] - rm);
            float fn = vnode ? (logp2 - rm - lg2f_(S0)) : NEG2;
#pragma unroll
            for (int b = 0; b < TN; b++) B[b] += fn;      // f2 was 0
            f2 = fn;
        }

        // ---- it1: full recompute (tight mb) + carry e for the chain ----
        {
            float rowS = 0.f;
#pragma unroll
            for (int b = 0; b < TN; b++) {
                float v = B[b];
                float mbb = warpmaxf(v);
                e[b] = ex2f(v - mbb + 26.f);
                unsigned u = __float2uint_rn(e[b]);
                unsigned s = __reduce_add_sync(FULL, u);
                rowS = fmaf(e[b], rcpf_((float)s), rowS);
            }
            float fn = vnode ? (f2 + CR - lg2f_(rowS)) : NEG2;
            float d = fn - f2;
            f2 = fn;
            float dmax = warpmaxf(vnode ? d : -3.0e38f);
            float tmul = ex2f(d - dmax);
#pragma unroll
            for (int b = 0; b < TN; b++) { B[b] += d; e[b] *= tmul; }
        }

        // ---- it2..18: incremental with exact carry; refresh mb at it8/it14 --
#pragma unroll 1
        for (int it = 2; it < 19; it++) {
            float rowS = 0.f;
            if (it == 8 || it == 14) {
                // full recompute: re-tighten implicit mb (resolution insurance)
#pragma unroll
                for (int b = 0; b < TN; b++) {
                    float v = B[b];
                    float mbb = warpmaxf(v);
                    e[b] = ex2f(v - mbb + 26.f);
                    unsigned u = __float2uint_rn(e[b]);
                    unsigned s = __reduce_add_sync(FULL, u);
                    rowS = fmaf(e[b], rcpf_((float)s), rowS);
                }
            } else {
#pragma unroll
                for (int b = 0; b < TN; b++) {
                    unsigned u = __float2uint_rn(e[b]);
                    unsigned s = __reduce_add_sync(FULL, u);
                    float sf = fmaxf((float)s, 1.0f);       // NaN guard
                    rowS = fmaf(e[b], rcpf_(sf), rowS);
                }
            }
            rowS = fmaxf(rowS, 1e-35f);                     // NaN guard
            float fn = vnode ? (f2 + CR - lg2f_(rowS)) : NEG2;
            float d = fn - f2;
            f2 = fn;
            float dmax = warpmaxf(vnode ? d : -3.0e38f);
            float tmul = ex2f(d - dmax);
#pragma unroll
            for (int b = 0; b < TN; b++) { B[b] += d; e[b] *= tmul; }
        }

        // ---- it19: incremental + direct T update: T = 0.1*(e/s)*2^d --------
        {
            float term[TN];
            float rowS = 0.f;
#pragma unroll
            for (int b = 0; b < TN; b++) {
                unsigned u = __float2uint_rn(e[b]);
                unsigned s = __reduce_add_sync(FULL, u);
                float sf = fmaxf((float)s, 1.0f);
                term[b] = e[b] * rcpf_(sf);                 // e_b / s_b
                rowS += term[b];
            }
            rowS = fmaxf(rowS, 1e-35f);
            float fn = vnode ? (f2 + CR - lg2f_(rowS)) : NEG2;
            float d = fn - f2;
            float sc = 0.1f * ex2f(d);
            float gam = 2.0f / ((float)k + 2.0f);
            float omg = 1.0f - gam;
            if (vlane) {
#pragma unroll
                for (int b = 0; b < TN; b++)
                    Trow[b] = omg * Trow[b] + gam * (sc * term[b]);
            }
        }
        __syncwarp();
        if (vlane) {
#pragma unroll
            for (int b = 0; b < TN; b++) sT[w][lane][b] = Trow[b];
        }
        __syncwarp();
    }
}

extern "C" void kernel_launch(void* const* d_in, const int* in_sizes, int n_in,
                              void* d_out, int out_size) {
    const float* x   = (const float*)d_in[0];
    const int*   ei  = (const int*)d_in[1];
    const float* tpl = (const float*)d_in[2];
    const float* tf  = (const float*)d_in[3];
    float* out = (float*)d_out;
    int n = in_sizes[0] / DD;
    int e = in_sizes[1] / 2;

    k_init<<<(n + 255) / 256, 256>>>(ei, n);
    k_bucket<<<(e + 255) / 256, 256>>>(ei, e);
    k_select<<<(n + 127) / 128, 128>>>(ei, n, e);
    k_c1<<<(n + 3) / 4, 128>>>(n);
    k_M<<<n, 128>>>(x, tf, n);
    int pairs = n * NT;
    k_fgw<<<(pairs + 3) / 4, 128>>>(tpl, out, n);
}

// round 11
// speedup vs baseline: 1.7008x; 1.7008x over previous
#include <cuda_runtime.h>
#include <math.h>
#include <stdint.h>

#define NMAXN 10000
#define NT 10
#define TN 10
#define KNB 16
#define K1 17
#define MAXB 128
#define DD 128
#define FULL 0xffffffffu
#define NEG2 -1.0e9f
#define LK2C (-14.426950408889634f)   /* -(1/REG)*log2(e), REG=0.1 */
#define LQ2C (-3.3219280948873623f)   /* log2(1/10) */
#define C26  (LQ2C + 26.0f)

// ---------------- device scratch (g_cnt statically zeroed; k_fgw re-zeroes) --
__device__ int g_cnt[NMAXN];                    // zero-init at load
__device__ int g_bucket[NMAXN * MAXB];
__device__ int g_nbrs[NMAXN * KNB];
__device__ int g_cnt16[NMAXN];
__device__ unsigned g_c1[NMAXN * K1];
__device__ float g_M[(size_t)NMAXN * NT * K1 * TN];   // [pair][a][b], 68 MB

__device__ __forceinline__ float ex2f(float x) {
    float r; asm("ex2.approx.ftz.f32 %0, %1;" : "=f"(r) : "f"(x)); return r;
}
__device__ __forceinline__ float lg2f_(float x) {
    float r; asm("lg2.approx.ftz.f32 %0, %1;" : "=f"(r) : "f"(x)); return r;
}
__device__ __forceinline__ float rcpf_(float x) {
    float r; asm("rcp.approx.ftz.f32 %0, %1;" : "=f"(r) : "f"(x)); return r;
}
// warp max of f32 via order-preserving int mapping + integer redux
__device__ __forceinline__ float warpmaxf(float v) {
    unsigned b = __float_as_uint(v);
    unsigned key = ((int)b < 0) ? ~b : (b ^ 0x80000000u);
    unsigned r = __reduce_max_sync(FULL, key);
    unsigned rb = (r & 0x80000000u) ? (r ^ 0x80000000u) : ~r;
    return __uint_as_float(rb);
}
// int64 edge_index (viewed as int32 pairs) has zero high words
__device__ __forceinline__ int detect64(const int* ei) {
    int ok = 1;
#pragma unroll
    for (int j = 0; j < 8; j++) ok &= (ei[2 * j + 1] == 0);
    return ok;
}

// ---------------- launch 1: bucket edges by src (g_cnt pre-zeroed) -----------
__global__ void k_bucket(const int* ei, int e) {
    int t = blockIdx.x * blockDim.x + threadIdx.x;
    if (t >= e) return;
    int is64 = detect64(ei);
    int s = is64 ? ei[2 * t] : ei[t];
    int pos = atomicAdd(&g_cnt[s], 1);
    if (pos < MAXB) g_bucket[s * MAXB + pos] = t;
}

// ------ launch 2: per node keep dsts of the 16 smallest edge indices ---------
__global__ void k_select(const int* ei, int n, int e) {
    int i = blockIdx.x * blockDim.x + threadIdx.x;
    if (i >= n) return;
    int is64 = detect64(ei);
    int c = g_cnt[i]; if (c > MAXB) c = MAXB;
    int arr[MAXB];
    for (int j = 0; j < c; j++) arr[j] = g_bucket[i * MAXB + j];
    int k16 = c < KNB ? c : KNB;
    for (int k = 0; k < k16; k++) {
        int mp = k;
        for (int j = k + 1; j < c; j++) if (arr[j] < arr[mp]) mp = j;
        int t = arr[k]; arr[k] = arr[mp]; arr[mp] = t;
        int eidx = arr[k];
        int dst = is64 ? ei[2 * (e + eidx)] : ei[e + eidx];
        g_nbrs[i * KNB + k] = dst;
    }
    g_cnt16[i] = k16;
}

// ---- launch 3: block per node: C1 adjacency bitmasks (warp 0) + M tile ------
__global__ void __launch_bounds__(128) k_c1M(const float* __restrict__ x,
                                             const float* __restrict__ tf, int n) {
    __shared__ float xs[K1][DD];
    __shared__ float sxn[K1];
    __shared__ int sS[K1];
    int i = blockIdx.x, tid = threadIdx.x;
    int wid = tid / 32, lane = tid % 32;
    int c16 = g_cnt16[i];

    // ---- warp 0: C1 masks (same algorithm as old k_c1) ----
    if (wid == 0) {
        int myid = -1;
        if (lane == 0) myid = i;
        else if (lane < K1 && (lane - 1) < c16) myid = g_nbrs[i * KNB + lane - 1];
        int cA = (myid >= 0) ? g_cnt16[myid] : 0;
        int nb[KNB];
#pragma unroll
        for (int j = 0; j < KNB; j++)
            nb[j] = (myid >= 0 && j < cA) ? g_nbrs[myid * KNB + j] : -2;
        unsigned msk = 0u;
#pragma unroll
        for (int b = 0; b < K1; b++) {
            int sb = __shfl_sync(FULL, myid, b);
            bool hit = false;
#pragma unroll
            for (int j = 0; j < KNB; j++) hit |= (nb[j] == sb);
            if (myid >= 0 && sb >= 0 && hit) msk |= (1u << b);
        }
        if (lane < K1) g_c1[i * K1 + lane] = msk;
    }

    // ---- all threads: M tile ----
    if (tid < K1) {
        int v;
        if (tid == 0) v = i;
        else v = (tid - 1 < c16) ? g_nbrs[i * KNB + tid - 1] : -1;
        sS[tid] = v;
    }
    __syncthreads();
    for (int a = 0; a < K1; a++) {
        int sv = sS[a];
        xs[a][tid] = (sv >= 0) ? x[(size_t)sv * DD + tid] : 0.f;
    }
    __syncthreads();
    if (tid < K1) {
        float s = 0.f;
        for (int d = 0; d < DD; d++) { float v = xs[tid][d]; s = fmaf(v, v, s); }
        sxn[tid] = s;
    }
    __syncthreads();
    if (tid < NT * TN) {
        int tt = tid / TN, b = tid % TN;
        const float4* fr = reinterpret_cast<const float4*>(tf + ((size_t)tt * TN + b) * DD);
        float acc[K1];
        float fb = 0.f;
#pragma unroll
        for (int a = 0; a < K1; a++) acc[a] = 0.f;
        for (int c = 0; c < DD / 4; c++) {
            float4 f4 = __ldg(fr + c);
            fb = fmaf(f4.x, f4.x, fmaf(f4.y, f4.y, fmaf(f4.z, f4.z, fmaf(f4.w, f4.w, fb))));
#pragma unroll
            for (int a = 0; a < K1; a++) {
                float4 x4 = *reinterpret_cast<const float4*>(&xs[a][c * 4]);
                acc[a] = fmaf(x4.x, f4.x, fmaf(x4.y, f4.y, fmaf(x4.z, f4.z, fmaf(x4.w, f4.w, acc[a]))));
            }
        }
        float* Mo = g_M + ((size_t)i * NT + tt) * (K1 * TN) + b;
#pragma unroll
        for (int a = 0; a < K1; a++) Mo[a * TN] = sxn[a] + fb - 2.f * acc[a];
    }
}

// ---------------- launch 4: FGW, warp per (node, template) -------------------
__global__ void __launch_bounds__(128) k_fgw(const float* __restrict__ C2g,
                                             float* __restrict__ out, int n) {
    __shared__ float sC2[NT][TN][TN];
    __shared__ float sc2r[NT][TN];
    __shared__ float sT[4][K1][TN];
    int tid = threadIdx.x;

    // re-zero g_cnt for the next kernel_launch call (keeps calls idempotent)
    int gid = blockIdx.x * 128 + tid;
    if (gid < NMAXN) g_cnt[gid] = 0;

    for (int idx = tid; idx < NT * TN * TN; idx += 128)
        (&sC2[0][0][0])[idx] = C2g[idx];
    __syncthreads();
    if (tid < NT * TN) {
        int tt = tid / TN, b = tid % TN;
        float s = 0.f;
        for (int c = 0; c < TN; c++) { float v = sC2[tt][b][c]; s = fmaf(v, v, s); }
        sc2r[tt][b] = s * (1.0f / TN);
    }
    __syncthreads();

    int w = tid >> 5, lane = tid & 31;
    long long pair = (long long)blockIdx.x * 4 + w;
    if (pair >= (long long)n * NT) return;
    int i = (int)(pair / NT), tt = (int)(pair % NT);

    int cnt1 = g_cnt16[i] + 1;
    bool vlane = lane < K1;
    bool vnode = lane < cnt1;
    float inv1 = 1.0f / (float)cnt1;
    unsigned m = vlane ? g_c1[i * K1 + lane] : 0u;
    const float* Mp = g_M + (size_t)pair * (K1 * TN) + lane * TN;   // L1-resident reloads
    float logp2 = vnode ? -log2f((float)cnt1) : NEG2;
    float CR = logp2 - LQ2C;
    float constC_a = (float)__popc(m) * inv1;

    float Trow[TN];
    float t0 = vnode ? (inv1 * (1.0f / TN)) : 0.f;
#pragma unroll
    for (int b = 0; b < TN; b++) Trow[b] = t0;
    if (vlane) {
#pragma unroll
        for (int b = 0; b < TN; b++) sT[w][lane][b] = Trow[b];
    }
    __syncwarp();

    for (int k = 0; k < 6; k++) {
        // tmp = C1 @ T (row a = my lane)
        float tmp[TN];
#pragma unroll
        for (int d = 0; d < TN; d++) tmp[d] = 0.f;
        for (int c = 0; c < K1; c++) {
            float wbit = (float)((m >> c) & 1u);
#pragma unroll
            for (int d = 0; d < TN; d++) tmp[d] = fmaf(wbit, sT[w][c][d], tmp[d]);
        }

        if (k == 5) {   // final distance
            float acc = 0.f;
            if (vlane) {
#pragma unroll
                for (int b = 0; b < TN; b++) {
                    float cr = 0.f;
#pragma unroll
                    for (int d = 0; d < TN; d++) cr = fmaf(tmp[d], sC2[tt][b][d], cr);
                    float tens = constC_a + sc2r[tt][b] - 2.f * cr;
                    acc += (0.5f * Mp[b] + 0.5f * tens) * Trow[b];
                }
            }
            for (int o = 16; o; o >>= 1) acc += __shfl_xor_sync(FULL, acc, o);
            if (lane == 0) out[pair] = acc;
            return;
        }

        // B = logK + f (f starts 0); pad lanes excluded via -1e30
        float B[TN], e[TN];
#pragma unroll
        for (int b = 0; b < TN; b++) {
            float cr = 0.f;
#pragma unroll
            for (int d = 0; d < TN; d++) cr = fmaf(tmp[d], sC2[tt][b][d], cr);
            float tens = constC_a + sc2r[tt][b] - 2.f * cr;
            B[b] = vlane ? (LK2C * (0.5f * Mp[b] + tens)) : -1e30f;
        }
        float f2 = 0.f;

        // ---- it0: full, max-based row step (rows unnormalized) ----
        {
            float g2[TN];
#pragma unroll
            for (int b = 0; b < TN; b++) {
                float v = B[b];
                float mbb = warpmaxf(v);
                float eb = ex2f(v - mbb + 26.f);          // max lane == 2^26 exact
                unsigned u = __float2uint_rn(eb);
                unsigned s = __reduce_add_sync(FULL, u);   // <= 17*2^26 < 2^32
                g2[b] = C26 - mbb - lg2f_((float)s);
            }
            float rm = -3.4e38f;
#pragma unroll
            for (int b = 0; b < TN; b++) { g2[b] += B[b]; rm = fmaxf(rm, g2[b]); }
            float S0 = 0.f;
#pragma unroll
            for (int b = 0; b < TN; b++) S0 += ex2f(g2[b] - rm);
            float fn = vnode ? (logp2 - rm - lg2f_(S0)) : NEG2;
#pragma unroll
            for (int b = 0; b < TN; b++) B[b] += fn;      // f2 was 0
            f2 = fn;
        }

        // ---- it1: full recompute (tight mb) + carry e for the chain ----
        {
            float rowS = 0.f;
#pragma unroll
            for (int b = 0; b < TN; b++) {
                float v = B[b];
                float mbb = warpmaxf(v);
                e[b] = ex2f(v - mbb + 26.f);
                unsigned u = __float2uint_rn(e[b]);
                unsigned s = __reduce_add_sync(FULL, u);
                rowS = fmaf(e[b], rcpf_((float)s), rowS);
            }
            float fn = vnode ? (f2 + CR - lg2f_(rowS)) : NEG2;
            float d = fn - f2;
            f2 = fn;
            float dmax = warpmaxf(vnode ? d : -3.0e38f);
            float tmul = ex2f(d - dmax);
#pragma unroll
            for (int b = 0; b < TN; b++) { B[b] += d; e[b] *= tmul; }
        }

        // ---- it2..18: incremental with exact carry; refresh mb at it8/it14 --
#pragma unroll 1
        for (int it = 2; it < 19; it++) {
            float rowS = 0.f;
            if (it == 8 || it == 14) {
                // full recompute: re-tighten implicit mb (resolution insurance)
#pragma unroll
                for (int b = 0; b < TN; b++) {
                    float v = B[b];
                    float mbb = warpmaxf(v);
                    e[b] = ex2f(v - mbb + 26.f);
                    unsigned u = __float2uint_rn(e[b]);
                    unsigned s = __reduce_add_sync(FULL, u);
                    rowS = fmaf(e[b], rcpf_((float)s), rowS);
                }
            } else {
#pragma unroll
                for (int b = 0; b < TN; b++) {
                    unsigned u = __float2uint_rn(e[b]);
                    unsigned s = __reduce_add_sync(FULL, u);
                    float sf = fmaxf((float)s, 1.0f);       // NaN guard
                    rowS = fmaf(e[b], rcpf_(sf), rowS);
                }
            }
            rowS = fmaxf(rowS, 1e-35f);                     // NaN guard
            float fn = vnode ? (f2 + CR - lg2f_(rowS)) : NEG2;
            float d = fn - f2;
            f2 = fn;
            float dmax = warpmaxf(vnode ? d : -3.0e38f);
            float tmul = ex2f(d - dmax);
#pragma unroll
            for (int b = 0; b < TN; b++) { B[b] += d; e[b] *= tmul; }
        }

        // ---- it19: incremental + direct T update: T = 0.1*(e/s)*2^d --------
        {
            float term[TN];
            float rowS = 0.f;
#pragma unroll
            for (int b = 0; b < TN; b++) {
                unsigned u = __float2uint_rn(e[b]);
                unsigned s = __reduce_add_sync(FULL, u);
                float sf = fmaxf((float)s, 1.0f);
                term[b] = e[b] * rcpf_(sf);                 // e_b / s_b
                rowS += term[b];
            }
            rowS = fmaxf(rowS, 1e-35f);
            float fn = vnode ? (f2 + CR - lg2f_(rowS)) : NEG2;
            float d = fn - f2;
            float sc = 0.1f * ex2f(d);
            float gam = 2.0f / ((float)k + 2.0f);
            float omg = 1.0f - gam;
            if (vlane) {
#pragma unroll
                for (int b = 0; b < TN; b++)
                    Trow[b] = omg * Trow[b] + gam * (sc * term[b]);
            }
        }
        __syncwarp();
        if (vlane) {
#pragma unroll
            for (int b = 0; b < TN; b++) sT[w][lane][b] = Trow[b];
        }
        __syncwarp();
    }
}

extern "C" void kernel_launch(void* const* d_in, const int* in_sizes, int n_in,
                              void* d_out, int out_size) {
    const float* x   = (const float*)d_in[0];
    const int*   ei  = (const int*)d_in[1];
    const float* tpl = (const float*)d_in[2];
    const float* tf  = (const float*)d_in[3];
    float* out = (float*)d_out;
    int n = in_sizes[0] / DD;
    int e = in_sizes[1] / 2;

    k_bucket<<<(e + 255) / 256, 256>>>(ei, e);
    k_select<<<(n + 127) / 128, 128>>>(ei, n, e);
    k_c1M<<<n, 128>>>(x, tf, n);
    int pairs = n * NT;
    k_fgw<<<(pairs + 3) / 4, 128>>>(tpl, out, n);
}